// round 14
// baseline (speedup 1.0000x reference)
#include <cuda_runtime.h>
#include <cstdint>

#define B_ 8
#define H_ 768
#define W_ 1024
#define H2_ 384
#define W2_ 512
#define H4_ 192
#define W4_ 256

typedef unsigned long long u64;

__device__ __forceinline__ u64 dup2(float v) {
  u64 r;
  asm("mov.b64 %0, {%1, %1};" : "=l"(r) : "f"(v));
  return r;
}
__device__ __forceinline__ u64 fma2(u64 a, u64 b, u64 c) {
  u64 d;
  asm("fma.rn.f32x2 %0, %1, %2, %3;" : "=l"(d) : "l"(a), "l"(b), "l"(c));
  return d;
}
__device__ __forceinline__ float2 unpk(u64 v) {
  float2 r;
  asm("mov.b64 {%0, %1}, %2;" : "=f"(r.x), "=f"(r.y) : "l"(v));
  return r;
}

// Scratch (device globals; no allocation allowed)
__device__ float g_buf1[(size_t)B_ * 20 * H2_ * W2_];
__device__ float g_buf2[(size_t)B_ * 40 * H4_ * W4_];
__device__ float g_buf3[(size_t)B_ * 20 * H4_ * W4_];

// ---------------------------------------------------------------------------
// K1: conv1 7x7 (3->20, pad3) + ReLU + 2x2 maxpool -> g_buf1
// Block 16x8. Thread: 1 pooled px (2x2 conv), co in 2 groups of 10.
// ci loop fully unrolled (3x) for cross-iteration LDS/FMA overlap.
// ---------------------------------------------------------------------------
__global__ __launch_bounds__(128, 6) void k1_conv1_pool(
    const float* __restrict__ in, const float* __restrict__ w1,
    const float* __restrict__ b1) {
  __shared__ __align__(16) float s_in[3 * 22 * 40];
  __shared__ __align__(16) float s_w[3 * 49 * 20];

  const int tx = threadIdx.x, ty = threadIdx.y;
  const int tid = ty * 16 + tx;
  const int bx = blockIdx.x, by = blockIdx.y, b = blockIdx.z;

  for (int idx = tid; idx < 2940; idx += 128) {
    int co = idx % 20, pos = idx / 20;
    s_w[idx] = w1[co * 147 + pos];
  }
  const float* inb = in + (size_t)b * 3 * H_ * W_;
  const int gy0 = 16 * by - 3, gx0 = 32 * bx - 3;
  for (int idx = tid; idx < 3 * 22 * 38; idx += 128) {
    int ci = idx / (22 * 38), rem = idx % (22 * 38);
    int r = rem / 38, c = rem % 38;
    int gy = gy0 + r, gx = gx0 + c;
    float v = 0.f;
    if ((unsigned)gy < (unsigned)H_ && (unsigned)gx < (unsigned)W_)
      v = inb[(size_t)ci * H_ * W_ + (size_t)gy * W_ + gx];
    s_in[ci * 22 * 40 + r * 40 + c] = v;
  }
  __syncthreads();

  const int oy = 8 * by + ty, ox = 16 * bx + tx;

  for (int g = 0; g < 2; ++g) {
    u64 acc[5][4];
#pragma unroll
    for (int c2 = 0; c2 < 5; ++c2)
#pragma unroll
      for (int p = 0; p < 4; ++p) acc[c2][p] = 0ull;

#pragma unroll
    for (int ci = 0; ci < 3; ++ci) {
#pragma unroll
      for (int ky = 0; ky < 7; ++ky) {
        const float* p0 = &s_in[ci * 22 * 40 + (2 * ty + ky) * 40 + 2 * tx];
        float a0[8], a1[8];
#pragma unroll
        for (int j = 0; j < 4; ++j) {
          float2 v = reinterpret_cast<const float2*>(p0)[j];
          a0[2 * j] = v.x; a0[2 * j + 1] = v.y;
          float2 u = reinterpret_cast<const float2*>(p0 + 40)[j];
          a1[2 * j] = u.x; a1[2 * j + 1] = u.y;
        }
        const float* wb = &s_w[(ci * 49 + ky * 7) * 20 + g * 10];
#pragma unroll
        for (int kx = 0; kx < 7; ++kx) {
          u64 w[5];
#pragma unroll
          for (int c2 = 0; c2 < 5; ++c2)
            w[c2] = *reinterpret_cast<const u64*>(wb + kx * 20 + 2 * c2);
          u64 d0 = dup2(a0[kx]), d1 = dup2(a0[kx + 1]);
          u64 d2 = dup2(a1[kx]), d3 = dup2(a1[kx + 1]);
#pragma unroll
          for (int c2 = 0; c2 < 5; ++c2) {
            acc[c2][0] = fma2(d0, w[c2], acc[c2][0]);
            acc[c2][1] = fma2(d1, w[c2], acc[c2][1]);
            acc[c2][2] = fma2(d2, w[c2], acc[c2][2]);
            acc[c2][3] = fma2(d3, w[c2], acc[c2][3]);
          }
        }
      }
    }

#pragma unroll
    for (int c2 = 0; c2 < 5; ++c2) {
      int co = g * 10 + 2 * c2;
      float2 v0 = unpk(acc[c2][0]), v1 = unpk(acc[c2][1]);
      float2 v2 = unpk(acc[c2][2]), v3 = unpk(acc[c2][3]);
      float mlo = fmaxf(fmaxf(v0.x, v1.x), fmaxf(v2.x, v3.x));
      float mhi = fmaxf(fmaxf(v0.y, v1.y), fmaxf(v2.y, v3.y));
      g_buf1[(((size_t)b * 20 + co) * H2_ + oy) * W2_ + ox] =
          fmaxf(mlo + __ldg(&b1[co]), 0.f);
      g_buf1[(((size_t)b * 20 + co + 1) * H2_ + oy) * W2_ + ox] =
          fmaxf(mhi + __ldg(&b1[co + 1]), 0.f);
    }
  }
}

// ---------------------------------------------------------------------------
// K2: conv2 5x5 (20->40, pad2) + ReLU + 2x2 maxpool -> g_buf2
// Block 16x8. Thread: 1 pooled px. co-group (10) via blockIdx.z.
// ci loop fully unrolled (5x).
// ---------------------------------------------------------------------------
__global__ __launch_bounds__(128, 6) void k2_conv2_pool(
    const float* __restrict__ w2, const float* __restrict__ b2) {
  __shared__ __align__(16) float s_in[5 * 20 * 38];
  __shared__ __align__(16) float s_w[5 * 25 * 10];

  const int tx = threadIdx.x, ty = threadIdx.y;
  const int tid = ty * 16 + tx;
  const int bx = blockIdx.x, by = blockIdx.y;
  const int b = blockIdx.z >> 2, g = blockIdx.z & 3;
  const float* inb = g_buf1 + (size_t)b * 20 * H2_ * W2_;
  const int oy = 8 * by + ty, ox = 16 * bx + tx;

  u64 acc[5][4];
#pragma unroll
  for (int c2 = 0; c2 < 5; ++c2)
#pragma unroll
    for (int p = 0; p < 4; ++p) acc[c2][p] = 0ull;

  for (int cc = 0; cc < 4; ++cc) {
    __syncthreads();
    const int gy0 = 16 * by - 2, gx0 = 32 * bx - 2;
    for (int idx = tid; idx < 5 * 20 * 36; idx += 128) {
      int ci = idx / (20 * 36), rem = idx % (20 * 36);
      int r = rem / 36, c = rem % 36;
      int gy = gy0 + r, gx = gx0 + c;
      float v = 0.f;
      if ((unsigned)gy < (unsigned)H2_ && (unsigned)gx < (unsigned)W2_)
        v = inb[(size_t)(cc * 5 + ci) * H2_ * W2_ + (size_t)gy * W2_ + gx];
      s_in[ci * 20 * 38 + r * 38 + c] = v;
    }
    for (int idx = tid; idx < 1250; idx += 128) {
      int c = idx % 10, k = (idx / 10) % 25, ci = idx / 250;
      s_w[idx] = w2[((size_t)(g * 10 + c) * 20 + cc * 5 + ci) * 25 + k];
    }
    __syncthreads();

#pragma unroll
    for (int ci = 0; ci < 5; ++ci) {
#pragma unroll
      for (int ky = 0; ky < 5; ++ky) {
        const float* p0 = &s_in[ci * 20 * 38 + (2 * ty + ky) * 38 + 2 * tx];
        float a0[6], a1[6];
#pragma unroll
        for (int j = 0; j < 3; ++j) {
          float2 v = reinterpret_cast<const float2*>(p0)[j];
          a0[2 * j] = v.x; a0[2 * j + 1] = v.y;
          float2 u = reinterpret_cast<const float2*>(p0 + 38)[j];
          a1[2 * j] = u.x; a1[2 * j + 1] = u.y;
        }
        const float* wb = &s_w[(ci * 25 + ky * 5) * 10];
#pragma unroll
        for (int kx = 0; kx < 5; ++kx) {
          u64 w[5];
#pragma unroll
          for (int c2 = 0; c2 < 5; ++c2)
            w[c2] = *reinterpret_cast<const u64*>(wb + kx * 10 + 2 * c2);
          u64 d0 = dup2(a0[kx]), d1 = dup2(a0[kx + 1]);
          u64 d2 = dup2(a1[kx]), d3 = dup2(a1[kx + 1]);
#pragma unroll
          for (int c2 = 0; c2 < 5; ++c2) {
            acc[c2][0] = fma2(d0, w[c2], acc[c2][0]);
            acc[c2][1] = fma2(d1, w[c2], acc[c2][1]);
            acc[c2][2] = fma2(d2, w[c2], acc[c2][2]);
            acc[c2][3] = fma2(d3, w[c2], acc[c2][3]);
          }
        }
      }
    }
  }

#pragma unroll
  for (int c2 = 0; c2 < 5; ++c2) {
    int co = g * 10 + 2 * c2;
    float2 v0 = unpk(acc[c2][0]), v1 = unpk(acc[c2][1]);
    float2 v2 = unpk(acc[c2][2]), v3 = unpk(acc[c2][3]);
    float mlo = fmaxf(fmaxf(v0.x, v1.x), fmaxf(v2.x, v3.x));
    float mhi = fmaxf(fmaxf(v0.y, v1.y), fmaxf(v2.y, v3.y));
    g_buf2[(((size_t)b * 40 + co) * H4_ + oy) * W4_ + ox] =
        fmaxf(mlo + __ldg(&b2[co]), 0.f);
    g_buf2[(((size_t)b * 40 + co + 1) * H4_ + oy) * W4_ + ox] =
        fmaxf(mhi + __ldg(&b2[co + 1]), 0.f);
  }
}

// ---------------------------------------------------------------------------
// K3: conv3 5x5 (40->20, pad2) + ReLU -> g_buf3
// Block 16x8. Thread: 2 px along x. Tile 32x8. co group via z.
// ci loop fully unrolled (4x).
// ---------------------------------------------------------------------------
__global__ __launch_bounds__(128, 8) void k3_conv3(
    const float* __restrict__ w3, const float* __restrict__ b3) {
  __shared__ __align__(16) float s_in[4 * 12 * 38];
  __shared__ __align__(16) float s_w[4 * 25 * 10];

  const int tx = threadIdx.x, ty = threadIdx.y;
  const int tid = ty * 16 + tx;
  const int bx = blockIdx.x, by = blockIdx.y;
  const int b = blockIdx.z >> 1, g = blockIdx.z & 1;
  const float* inb = g_buf2 + (size_t)b * 40 * H4_ * W4_;

  u64 acc[5][2];
#pragma unroll
  for (int c2 = 0; c2 < 5; ++c2) { acc[c2][0] = 0ull; acc[c2][1] = 0ull; }

  for (int cc = 0; cc < 10; ++cc) {
    __syncthreads();
    const int gy0 = 8 * by - 2, gx0 = 32 * bx - 2;
    for (int idx = tid; idx < 4 * 12 * 36; idx += 128) {
      int ci = idx / (12 * 36), rem = idx % (12 * 36);
      int r = rem / 36, c = rem % 36;
      int gy = gy0 + r, gx = gx0 + c;
      float v = 0.f;
      if ((unsigned)gy < (unsigned)H4_ && (unsigned)gx < (unsigned)W4_)
        v = inb[(size_t)(cc * 4 + ci) * H4_ * W4_ + (size_t)gy * W4_ + gx];
      s_in[ci * 12 * 38 + r * 38 + c] = v;
    }
    for (int idx = tid; idx < 1000; idx += 128) {
      int c = idx % 10, k = (idx / 10) % 25, ci = idx / 250;
      s_w[idx] = w3[((size_t)(g * 10 + c) * 40 + cc * 4 + ci) * 25 + k];
    }
    __syncthreads();

#pragma unroll
    for (int ci = 0; ci < 4; ++ci) {
#pragma unroll
      for (int ky = 0; ky < 5; ++ky) {
        const float* p0 = &s_in[ci * 12 * 38 + (ty + ky) * 38 + 2 * tx];
        float a[6];
#pragma unroll
        for (int j = 0; j < 3; ++j) {
          float2 v = reinterpret_cast<const float2*>(p0)[j];
          a[2 * j] = v.x; a[2 * j + 1] = v.y;
        }
        const float* wb = &s_w[(ci * 25 + ky * 5) * 10];
#pragma unroll
        for (int kx = 0; kx < 5; ++kx) {
          u64 w[5];
#pragma unroll
          for (int c2 = 0; c2 < 5; ++c2)
            w[c2] = *reinterpret_cast<const u64*>(wb + kx * 10 + 2 * c2);
          u64 d0 = dup2(a[kx]), d1 = dup2(a[kx + 1]);
#pragma unroll
          for (int c2 = 0; c2 < 5; ++c2) {
            acc[c2][0] = fma2(d0, w[c2], acc[c2][0]);
            acc[c2][1] = fma2(d1, w[c2], acc[c2][1]);
          }
        }
      }
    }
  }

  const int oy = 8 * by + ty;
#pragma unroll
  for (int c2 = 0; c2 < 5; ++c2) {
    int co = g * 10 + 2 * c2;
    float blo = __ldg(&b3[co]), bhi = __ldg(&b3[co + 1]);
#pragma unroll
    for (int p = 0; p < 2; ++p) {
      float2 v = unpk(acc[c2][p]);
      int ox = 32 * bx + 2 * tx + p;
      g_buf3[(((size_t)b * 20 + co) * H4_ + oy) * W4_ + ox] = fmaxf(v.x + blo, 0.f);
      g_buf3[(((size_t)b * 20 + co + 1) * H4_ + oy) * W4_ + ox] = fmaxf(v.y + bhi, 0.f);
    }
  }
}

// ---------------------------------------------------------------------------
// K4: conv4 5x5 (20->10) + ReLU, conv5 1x1 (10->1), gray residual, ReLU -> out
// ci loop fully unrolled (4x). Gray prefetch kept from R13 (neutral, harmless).
// ---------------------------------------------------------------------------
__global__ __launch_bounds__(128, 8) void k4_conv45_gray(
    const float* __restrict__ input, const float* __restrict__ w4,
    const float* __restrict__ b4, const float* __restrict__ w5,
    const float* __restrict__ b5, float* __restrict__ out) {
  __shared__ __align__(16) float s_in[4 * 12 * 38];
  __shared__ __align__(16) float s_w[4 * 25 * 10];

  const int tx = threadIdx.x, ty = threadIdx.y;
  const int tid = ty * 16 + tx;
  const int bx = blockIdx.x, by = blockIdx.y, b = blockIdx.z;
  const float* inb3 = g_buf3 + (size_t)b * 20 * H4_ * W4_;
  const int oy = 8 * by + ty;

  float gsum[2];
  {
    const float* ib = input + (size_t)b * 3 * H_ * W_;
    const int Y0 = 4 * oy + 1;
#pragma unroll
    for (int p = 0; p < 2; ++p) {
      const int ox = 32 * bx + 2 * tx + p;
      const int X0 = 4 * ox + 1;
      const float* q = ib + (size_t)Y0 * W_ + X0;
      float s0 = q[0] + q[1] + q[W_] + q[W_ + 1];
      q += (size_t)H_ * W_;
      float s1 = q[0] + q[1] + q[W_] + q[W_ + 1];
      q += (size_t)H_ * W_;
      float s2 = q[0] + q[1] + q[W_] + q[W_ + 1];
      gsum[p] = 0.25f * (0.299f * s0 + 0.587f * s1 + 0.114f * s2);
    }
  }

  u64 acc[5][2];
#pragma unroll
  for (int c2 = 0; c2 < 5; ++c2) { acc[c2][0] = 0ull; acc[c2][1] = 0ull; }

  for (int cc = 0; cc < 5; ++cc) {
    __syncthreads();
    const int gy0 = 8 * by - 2, gx0 = 32 * bx - 2;
    for (int idx = tid; idx < 4 * 12 * 36; idx += 128) {
      int ci = idx / (12 * 36), rem = idx % (12 * 36);
      int r = rem / 36, c = rem % 36;
      int gy = gy0 + r, gx = gx0 + c;
      float v = 0.f;
      if ((unsigned)gy < (unsigned)H4_ && (unsigned)gx < (unsigned)W4_)
        v = inb3[(size_t)(cc * 4 + ci) * H4_ * W4_ + (size_t)gy * W4_ + gx];
      s_in[ci * 12 * 38 + r * 38 + c] = v;
    }
    for (int idx = tid; idx < 1000; idx += 128) {
      int c = idx % 10, k = (idx / 10) % 25, ci = idx / 250;
      s_w[idx] = w4[((size_t)c * 20 + cc * 4 + ci) * 25 + k];
    }
    __syncthreads();

#pragma unroll
    for (int ci = 0; ci < 4; ++ci) {
#pragma unroll
      for (int ky = 0; ky < 5; ++ky) {
        const float* p0 = &s_in[ci * 12 * 38 + (ty + ky) * 38 + 2 * tx];
        float a[6];
#pragma unroll
        for (int j = 0; j < 3; ++j) {
          float2 v = reinterpret_cast<const float2*>(p0)[j];
          a[2 * j] = v.x; a[2 * j + 1] = v.y;
        }
        const float* wb = &s_w[(ci * 25 + ky * 5) * 10];
#pragma unroll
        for (int kx = 0; kx < 5; ++kx) {
          u64 w[5];
#pragma unroll
          for (int c2 = 0; c2 < 5; ++c2)
            w[c2] = *reinterpret_cast<const u64*>(wb + kx * 10 + 2 * c2);
          u64 d0 = dup2(a[kx]), d1 = dup2(a[kx + 1]);
#pragma unroll
          for (int c2 = 0; c2 < 5; ++c2) {
            acc[c2][0] = fma2(d0, w[c2], acc[c2][0]);
            acc[c2][1] = fma2(d1, w[c2], acc[c2][1]);
          }
        }
      }
    }
  }

  const float bias5 = __ldg(&b5[0]);
  float w5r[10], b4r[10];
#pragma unroll
  for (int c = 0; c < 10; ++c) {
    w5r[c] = __ldg(&w5[c]);
    b4r[c] = __ldg(&b4[c]);
  }

#pragma unroll
  for (int p = 0; p < 2; ++p) {
    float y = bias5;
#pragma unroll
    for (int c2 = 0; c2 < 5; ++c2) {
      float2 v = unpk(acc[c2][p]);
      y = fmaf(w5r[2 * c2], fmaxf(v.x + b4r[2 * c2], 0.f), y);
      y = fmaf(w5r[2 * c2 + 1], fmaxf(v.y + b4r[2 * c2 + 1], 0.f), y);
    }
    const int ox = 32 * bx + 2 * tx + p;
    out[((size_t)b * H4_ + oy) * W4_ + ox] =
        fmaxf(y + fmaxf(gsum[p], 0.f), 0.f);
  }
}

// ---------------------------------------------------------------------------
extern "C" void kernel_launch(void* const* d_in, const int* in_sizes, int n_in,
                              void* d_out, int out_size) {
  const float* input = (const float*)d_in[0];
  const float* w1 = (const float*)d_in[1];
  const float* b1 = (const float*)d_in[2];
  const float* w2 = (const float*)d_in[3];
  const float* b2 = (const float*)d_in[4];
  const float* w3 = (const float*)d_in[5];
  const float* b3 = (const float*)d_in[6];
  const float* w4 = (const float*)d_in[7];
  const float* b4 = (const float*)d_in[8];
  const float* w5 = (const float*)d_in[9];
  const float* b5 = (const float*)d_in[10];
  float* out = (float*)d_out;

  dim3 blk(16, 8);
  k1_conv1_pool<<<dim3(32, 48, B_), blk>>>(input, w1, b1);
  k2_conv2_pool<<<dim3(16, 24, 4 * B_), blk>>>(w2, b2);
  k3_conv3<<<dim3(8, 24, 2 * B_), blk>>>(w3, b3);
  k4_conv45_gray<<<dim3(8, 24, B_), blk>>>(input, w4, b4, w5, b5, out);
}

// round 15
// speedup vs baseline: 1.0792x; 1.0792x over previous
#include <cuda_runtime.h>
#include <cstdint>

#define B_ 8
#define H_ 768
#define W_ 1024
#define H2_ 384
#define W2_ 512
#define H4_ 192
#define W4_ 256

typedef unsigned long long u64;

__device__ __forceinline__ u64 dup2(float v) {
  u64 r;
  asm("mov.b64 %0, {%1, %1};" : "=l"(r) : "f"(v));
  return r;
}
__device__ __forceinline__ u64 fma2(u64 a, u64 b, u64 c) {
  u64 d;
  asm("fma.rn.f32x2 %0, %1, %2, %3;" : "=l"(d) : "l"(a), "l"(b), "l"(c));
  return d;
}
__device__ __forceinline__ float2 unpk(u64 v) {
  float2 r;
  asm("mov.b64 {%0, %1}, %2;" : "=f"(r.x), "=f"(r.y) : "l"(v));
  return r;
}
__device__ __forceinline__ uint32_t smem_u32(const void* p) {
  uint32_t a;
  asm("{ .reg .u64 t; cvta.to.shared.u64 t, %1; cvt.u32.u64 %0, t; }"
      : "=r"(a) : "l"(p));
  return a;
}
__device__ __forceinline__ void cp_async8(uint32_t saddr, const float* gptr,
                                          int srcsz) {
  asm volatile("cp.async.ca.shared.global [%0], [%1], 8, %2;"
               :: "r"(saddr), "l"(gptr), "r"(srcsz));
}
#define CP_COMMIT() asm volatile("cp.async.commit_group;" ::: "memory")
#define CP_WAIT0() asm volatile("cp.async.wait_group 0;" ::: "memory")

// Scratch (device globals; no allocation allowed)
__device__ float g_buf1[(size_t)B_ * 20 * H2_ * W2_];
__device__ float g_buf2[(size_t)B_ * 40 * H4_ * W4_];
__device__ float g_buf3[(size_t)B_ * 20 * H4_ * W4_];

// ---------------------------------------------------------------------------
// K1: conv1 7x7 (3->20, pad3) + ReLU + 2x2 maxpool -> g_buf1  (R6 exact)
// ---------------------------------------------------------------------------
__global__ __launch_bounds__(128, 6) void k1_conv1_pool(
    const float* __restrict__ in, const float* __restrict__ w1,
    const float* __restrict__ b1) {
  __shared__ __align__(16) float s_in[3 * 22 * 40];
  __shared__ __align__(16) float s_w[3 * 49 * 20];

  const int tx = threadIdx.x, ty = threadIdx.y;
  const int tid = ty * 16 + tx;
  const int bx = blockIdx.x, by = blockIdx.y, b = blockIdx.z;

  for (int idx = tid; idx < 2940; idx += 128) {
    int co = idx % 20, pos = idx / 20;
    s_w[idx] = w1[co * 147 + pos];
  }
  const float* inb = in + (size_t)b * 3 * H_ * W_;
  const int gy0 = 16 * by - 3, gx0 = 32 * bx - 3;
  for (int idx = tid; idx < 3 * 22 * 38; idx += 128) {
    int ci = idx / (22 * 38), rem = idx % (22 * 38);
    int r = rem / 38, c = rem % 38;
    int gy = gy0 + r, gx = gx0 + c;
    float v = 0.f;
    if ((unsigned)gy < (unsigned)H_ && (unsigned)gx < (unsigned)W_)
      v = inb[(size_t)ci * H_ * W_ + (size_t)gy * W_ + gx];
    s_in[ci * 22 * 40 + r * 40 + c] = v;
  }
  __syncthreads();

  const int oy = 8 * by + ty, ox = 16 * bx + tx;

  for (int g = 0; g < 2; ++g) {
    u64 acc[5][4];
#pragma unroll
    for (int c2 = 0; c2 < 5; ++c2)
#pragma unroll
      for (int p = 0; p < 4; ++p) acc[c2][p] = 0ull;

#pragma unroll 1
    for (int ci = 0; ci < 3; ++ci) {
#pragma unroll
      for (int ky = 0; ky < 7; ++ky) {
        const float* p0 = &s_in[ci * 22 * 40 + (2 * ty + ky) * 40 + 2 * tx];
        float a0[8], a1[8];
#pragma unroll
        for (int j = 0; j < 4; ++j) {
          float2 v = reinterpret_cast<const float2*>(p0)[j];
          a0[2 * j] = v.x; a0[2 * j + 1] = v.y;
          float2 u = reinterpret_cast<const float2*>(p0 + 40)[j];
          a1[2 * j] = u.x; a1[2 * j + 1] = u.y;
        }
        const float* wb = &s_w[(ci * 49 + ky * 7) * 20 + g * 10];
#pragma unroll
        for (int kx = 0; kx < 7; ++kx) {
          u64 w[5];
#pragma unroll
          for (int c2 = 0; c2 < 5; ++c2)
            w[c2] = *reinterpret_cast<const u64*>(wb + kx * 20 + 2 * c2);
          u64 d0 = dup2(a0[kx]), d1 = dup2(a0[kx + 1]);
          u64 d2 = dup2(a1[kx]), d3 = dup2(a1[kx + 1]);
#pragma unroll
          for (int c2 = 0; c2 < 5; ++c2) {
            acc[c2][0] = fma2(d0, w[c2], acc[c2][0]);
            acc[c2][1] = fma2(d1, w[c2], acc[c2][1]);
            acc[c2][2] = fma2(d2, w[c2], acc[c2][2]);
            acc[c2][3] = fma2(d3, w[c2], acc[c2][3]);
          }
        }
      }
    }

#pragma unroll
    for (int c2 = 0; c2 < 5; ++c2) {
      int co = g * 10 + 2 * c2;
      float2 v0 = unpk(acc[c2][0]), v1 = unpk(acc[c2][1]);
      float2 v2 = unpk(acc[c2][2]), v3 = unpk(acc[c2][3]);
      float mlo = fmaxf(fmaxf(v0.x, v1.x), fmaxf(v2.x, v3.x));
      float mhi = fmaxf(fmaxf(v0.y, v1.y), fmaxf(v2.y, v3.y));
      g_buf1[(((size_t)b * 20 + co) * H2_ + oy) * W2_ + ox] =
          fmaxf(mlo + __ldg(&b1[co]), 0.f);
      g_buf1[(((size_t)b * 20 + co + 1) * H2_ + oy) * W2_ + ox] =
          fmaxf(mhi + __ldg(&b1[co + 1]), 0.f);
    }
  }
}

// ---------------------------------------------------------------------------
// K2: conv2 5x5 (20->40, pad2) + ReLU + 2x2 maxpool -> g_buf2
// Double-buffered s_in via cp.async; compute of chunk cc overlaps fill of cc+1.
// ---------------------------------------------------------------------------
#define K2_CH (5 * 20 * 38)  // floats per buffer

__global__ __launch_bounds__(128, 6) void k2_conv2_pool(
    const float* __restrict__ w2, const float* __restrict__ b2) {
  __shared__ __align__(16) float s_in[2][K2_CH];
  __shared__ __align__(16) float s_w[5 * 25 * 10];

  const int tx = threadIdx.x, ty = threadIdx.y;
  const int tid = ty * 16 + tx;
  const int bx = blockIdx.x, by = blockIdx.y;
  const int b = blockIdx.z >> 2, g = blockIdx.z & 3;
  const float* inb = g_buf1 + (size_t)b * 20 * H2_ * W2_;
  const int oy = 8 * by + ty, ox = 16 * bx + tx;
  const int gy0 = 16 * by - 2, gx0 = 32 * bx - 2;
  const uint32_t sin_base = smem_u32(s_in);

  // issue chunk cc into buffer bufi: 5 ci x 20 r x 18 granules (2 floats each)
  auto issue = [&](int cc, int bufi) {
    for (int idx = tid; idx < 1800; idx += 128) {
      int ci = idx / 360, rem = idx % 360;
      int r = rem / 18, j = rem % 18;
      int gy = gy0 + r, gx = gx0 + 2 * j;
      bool ok = (unsigned)gy < (unsigned)H2_ && (unsigned)gx < (unsigned)W2_;
      const float* src = inb + (size_t)(cc * 5 + ci) * H2_ * W2_ +
                         (size_t)(ok ? gy : 0) * W2_ + (ok ? gx : 0);
      uint32_t dst =
          sin_base + (uint32_t)(bufi * K2_CH + ci * 20 * 38 + r * 38 + 2 * j) * 4u;
      cp_async8(dst, src, ok ? 8 : 0);
    }
    CP_COMMIT();
  };

  u64 acc[5][4];
#pragma unroll
  for (int c2 = 0; c2 < 5; ++c2)
#pragma unroll
    for (int p = 0; p < 4; ++p) acc[c2][p] = 0ull;

  issue(0, 0);

  for (int cc = 0; cc < 4; ++cc) {
    // s_w for this chunk (plain); previous compute finished at end-of-loop sync
    for (int idx = tid; idx < 1250; idx += 128) {
      int c = idx % 10, k = (idx / 10) % 25, ci = idx / 250;
      s_w[idx] = w2[((size_t)(g * 10 + c) * 20 + cc * 5 + ci) * 25 + k];
    }
    CP_WAIT0();
    __syncthreads();
    if (cc < 3) issue(cc + 1, (cc + 1) & 1);

    const float* buf = s_in[cc & 1];
#pragma unroll 1
    for (int ci = 0; ci < 5; ++ci) {
#pragma unroll
      for (int ky = 0; ky < 5; ++ky) {
        const float* p0 = &buf[ci * 20 * 38 + (2 * ty + ky) * 38 + 2 * tx];
        float a0[6], a1[6];
#pragma unroll
        for (int j = 0; j < 3; ++j) {
          float2 v = reinterpret_cast<const float2*>(p0)[j];
          a0[2 * j] = v.x; a0[2 * j + 1] = v.y;
          float2 u = reinterpret_cast<const float2*>(p0 + 38)[j];
          a1[2 * j] = u.x; a1[2 * j + 1] = u.y;
        }
        const float* wb = &s_w[(ci * 25 + ky * 5) * 10];
#pragma unroll
        for (int kx = 0; kx < 5; ++kx) {
          u64 w[5];
#pragma unroll
          for (int c2 = 0; c2 < 5; ++c2)
            w[c2] = *reinterpret_cast<const u64*>(wb + kx * 10 + 2 * c2);
          u64 d0 = dup2(a0[kx]), d1 = dup2(a0[kx + 1]);
          u64 d2 = dup2(a1[kx]), d3 = dup2(a1[kx + 1]);
#pragma unroll
          for (int c2 = 0; c2 < 5; ++c2) {
            acc[c2][0] = fma2(d0, w[c2], acc[c2][0]);
            acc[c2][1] = fma2(d1, w[c2], acc[c2][1]);
            acc[c2][2] = fma2(d2, w[c2], acc[c2][2]);
            acc[c2][3] = fma2(d3, w[c2], acc[c2][3]);
          }
        }
      }
    }
    __syncthreads();
  }

#pragma unroll
  for (int c2 = 0; c2 < 5; ++c2) {
    int co = g * 10 + 2 * c2;
    float2 v0 = unpk(acc[c2][0]), v1 = unpk(acc[c2][1]);
    float2 v2 = unpk(acc[c2][2]), v3 = unpk(acc[c2][3]);
    float mlo = fmaxf(fmaxf(v0.x, v1.x), fmaxf(v2.x, v3.x));
    float mhi = fmaxf(fmaxf(v0.y, v1.y), fmaxf(v2.y, v3.y));
    g_buf2[(((size_t)b * 40 + co) * H4_ + oy) * W4_ + ox] =
        fmaxf(mlo + __ldg(&b2[co]), 0.f);
    g_buf2[(((size_t)b * 40 + co + 1) * H4_ + oy) * W4_ + ox] =
        fmaxf(mhi + __ldg(&b2[co + 1]), 0.f);
  }
}

// ---------------------------------------------------------------------------
// K3: conv3 5x5 (40->20, pad2) + ReLU -> g_buf3
// Double-buffered s_in via cp.async. 10 chunks of 4 ci.
// ---------------------------------------------------------------------------
#define K34_CH (4 * 12 * 38)

__global__ __launch_bounds__(128, 8) void k3_conv3(
    const float* __restrict__ w3, const float* __restrict__ b3) {
  __shared__ __align__(16) float s_in[2][K34_CH];
  __shared__ __align__(16) float s_w[4 * 25 * 10];

  const int tx = threadIdx.x, ty = threadIdx.y;
  const int tid = ty * 16 + tx;
  const int bx = blockIdx.x, by = blockIdx.y;
  const int b = blockIdx.z >> 1, g = blockIdx.z & 1;
  const float* inb = g_buf2 + (size_t)b * 40 * H4_ * W4_;
  const int gy0 = 8 * by - 2, gx0 = 32 * bx - 2;
  const uint32_t sin_base = smem_u32(s_in);

  auto issue = [&](int cc, int bufi) {
    for (int idx = tid; idx < 864; idx += 128) {
      int ci = idx / 216, rem = idx % 216;
      int r = rem / 18, j = rem % 18;
      int gy = gy0 + r, gx = gx0 + 2 * j;
      bool ok = (unsigned)gy < (unsigned)H4_ && (unsigned)gx < (unsigned)W4_;
      const float* src = inb + (size_t)(cc * 4 + ci) * H4_ * W4_ +
                         (size_t)(ok ? gy : 0) * W4_ + (ok ? gx : 0);
      uint32_t dst =
          sin_base + (uint32_t)(bufi * K34_CH + ci * 12 * 38 + r * 38 + 2 * j) * 4u;
      cp_async8(dst, src, ok ? 8 : 0);
    }
    CP_COMMIT();
  };

  u64 acc[5][2];
#pragma unroll
  for (int c2 = 0; c2 < 5; ++c2) { acc[c2][0] = 0ull; acc[c2][1] = 0ull; }

  issue(0, 0);

  for (int cc = 0; cc < 10; ++cc) {
    for (int idx = tid; idx < 1000; idx += 128) {
      int c = idx % 10, k = (idx / 10) % 25, ci = idx / 250;
      s_w[idx] = w3[((size_t)(g * 10 + c) * 40 + cc * 4 + ci) * 25 + k];
    }
    CP_WAIT0();
    __syncthreads();
    if (cc < 9) issue(cc + 1, (cc + 1) & 1);

    const float* buf = s_in[cc & 1];
#pragma unroll 1
    for (int ci = 0; ci < 4; ++ci) {
#pragma unroll
      for (int ky = 0; ky < 5; ++ky) {
        const float* p0 = &buf[ci * 12 * 38 + (ty + ky) * 38 + 2 * tx];
        float a[6];
#pragma unroll
        for (int j = 0; j < 3; ++j) {
          float2 v = reinterpret_cast<const float2*>(p0)[j];
          a[2 * j] = v.x; a[2 * j + 1] = v.y;
        }
        const float* wb = &s_w[(ci * 25 + ky * 5) * 10];
#pragma unroll
        for (int kx = 0; kx < 5; ++kx) {
          u64 w[5];
#pragma unroll
          for (int c2 = 0; c2 < 5; ++c2)
            w[c2] = *reinterpret_cast<const u64*>(wb + kx * 10 + 2 * c2);
          u64 d0 = dup2(a[kx]), d1 = dup2(a[kx + 1]);
#pragma unroll
          for (int c2 = 0; c2 < 5; ++c2) {
            acc[c2][0] = fma2(d0, w[c2], acc[c2][0]);
            acc[c2][1] = fma2(d1, w[c2], acc[c2][1]);
          }
        }
      }
    }
    __syncthreads();
  }

  const int oy = 8 * by + ty;
#pragma unroll
  for (int c2 = 0; c2 < 5; ++c2) {
    int co = g * 10 + 2 * c2;
    float blo = __ldg(&b3[co]), bhi = __ldg(&b3[co + 1]);
#pragma unroll
    for (int p = 0; p < 2; ++p) {
      float2 v = unpk(acc[c2][p]);
      int ox = 32 * bx + 2 * tx + p;
      g_buf3[(((size_t)b * 20 + co) * H4_ + oy) * W4_ + ox] = fmaxf(v.x + blo, 0.f);
      g_buf3[(((size_t)b * 20 + co + 1) * H4_ + oy) * W4_ + ox] = fmaxf(v.y + bhi, 0.f);
    }
  }
}

// ---------------------------------------------------------------------------
// K4: conv4 5x5 (20->10) + ReLU, conv5 1x1 (10->1), gray residual, ReLU -> out
// Double-buffered s_in via cp.async. 5 chunks of 4 ci.
// ---------------------------------------------------------------------------
__global__ __launch_bounds__(128, 8) void k4_conv45_gray(
    const float* __restrict__ input, const float* __restrict__ w4,
    const float* __restrict__ b4, const float* __restrict__ w5,
    const float* __restrict__ b5, float* __restrict__ out) {
  __shared__ __align__(16) float s_in[2][K34_CH];
  __shared__ __align__(16) float s_w[4 * 25 * 10];

  const int tx = threadIdx.x, ty = threadIdx.y;
  const int tid = ty * 16 + tx;
  const int bx = blockIdx.x, by = blockIdx.y, b = blockIdx.z;
  const float* inb3 = g_buf3 + (size_t)b * 20 * H4_ * W4_;
  const int oy = 8 * by + ty;
  const int gy0 = 8 * by - 2, gx0 = 32 * bx - 2;
  const uint32_t sin_base = smem_u32(s_in);

  auto issue = [&](int cc, int bufi) {
    for (int idx = tid; idx < 864; idx += 128) {
      int ci = idx / 216, rem = idx % 216;
      int r = rem / 18, j = rem % 18;
      int gy = gy0 + r, gx = gx0 + 2 * j;
      bool ok = (unsigned)gy < (unsigned)H4_ && (unsigned)gx < (unsigned)W4_;
      const float* src = inb3 + (size_t)(cc * 4 + ci) * H4_ * W4_ +
                         (size_t)(ok ? gy : 0) * W4_ + (ok ? gx : 0);
      uint32_t dst =
          sin_base + (uint32_t)(bufi * K34_CH + ci * 12 * 38 + r * 38 + 2 * j) * 4u;
      cp_async8(dst, src, ok ? 8 : 0);
    }
    CP_COMMIT();
  };

  u64 acc[5][2];
#pragma unroll
  for (int c2 = 0; c2 < 5; ++c2) { acc[c2][0] = 0ull; acc[c2][1] = 0ull; }

  issue(0, 0);

  for (int cc = 0; cc < 5; ++cc) {
    for (int idx = tid; idx < 1000; idx += 128) {
      int c = idx % 10, k = (idx / 10) % 25, ci = idx / 250;
      s_w[idx] = w4[((size_t)c * 20 + cc * 4 + ci) * 25 + k];
    }
    CP_WAIT0();
    __syncthreads();
    if (cc < 4) issue(cc + 1, (cc + 1) & 1);

    const float* buf = s_in[cc & 1];
#pragma unroll 1
    for (int ci = 0; ci < 4; ++ci) {
#pragma unroll
      for (int ky = 0; ky < 5; ++ky) {
        const float* p0 = &buf[ci * 12 * 38 + (ty + ky) * 38 + 2 * tx];
        float a[6];
#pragma unroll
        for (int j = 0; j < 3; ++j) {
          float2 v = reinterpret_cast<const float2*>(p0)[j];
          a[2 * j] = v.x; a[2 * j + 1] = v.y;
        }
        const float* wb = &s_w[(ci * 25 + ky * 5) * 10];
#pragma unroll
        for (int kx = 0; kx < 5; ++kx) {
          u64 w[5];
#pragma unroll
          for (int c2 = 0; c2 < 5; ++c2)
            w[c2] = *reinterpret_cast<const u64*>(wb + kx * 10 + 2 * c2);
          u64 d0 = dup2(a[kx]), d1 = dup2(a[kx + 1]);
#pragma unroll
          for (int c2 = 0; c2 < 5; ++c2) {
            acc[c2][0] = fma2(d0, w[c2], acc[c2][0]);
            acc[c2][1] = fma2(d1, w[c2], acc[c2][1]);
          }
        }
      }
    }
    __syncthreads();
  }

  const float* ib = input + (size_t)b * 3 * H_ * W_;
  const float bias5 = __ldg(&b5[0]);
  float w5r[10], b4r[10];
#pragma unroll
  for (int c = 0; c < 10; ++c) {
    w5r[c] = __ldg(&w5[c]);
    b4r[c] = __ldg(&b4[c]);
  }

#pragma unroll
  for (int p = 0; p < 2; ++p) {
    float y = bias5;
#pragma unroll
    for (int c2 = 0; c2 < 5; ++c2) {
      float2 v = unpk(acc[c2][p]);
      y = fmaf(w5r[2 * c2], fmaxf(v.x + b4r[2 * c2], 0.f), y);
      y = fmaf(w5r[2 * c2 + 1], fmaxf(v.y + b4r[2 * c2 + 1], 0.f), y);
    }
    const int ox = 32 * bx + 2 * tx + p;
    const int Y0 = 4 * oy + 1, X0 = 4 * ox + 1;
    const float* q = ib + (size_t)Y0 * W_ + X0;
    float s0 = q[0] + q[1] + q[W_] + q[W_ + 1];
    q += (size_t)H_ * W_;
    float s1 = q[0] + q[1] + q[W_] + q[W_ + 1];
    q += (size_t)H_ * W_;
    float s2 = q[0] + q[1] + q[W_] + q[W_ + 1];
    float gsum = 0.25f * (0.299f * s0 + 0.587f * s1 + 0.114f * s2);
    out[((size_t)b * H4_ + oy) * W4_ + ox] = fmaxf(y + fmaxf(gsum, 0.f), 0.f);
  }
}

// ---------------------------------------------------------------------------
extern "C" void kernel_launch(void* const* d_in, const int* in_sizes, int n_in,
                              void* d_out, int out_size) {
  const float* input = (const float*)d_in[0];
  const float* w1 = (const float*)d_in[1];
  const float* b1 = (const float*)d_in[2];
  const float* w2 = (const float*)d_in[3];
  const float* b2 = (const float*)d_in[4];
  const float* w3 = (const float*)d_in[5];
  const float* b3 = (const float*)d_in[6];
  const float* w4 = (const float*)d_in[7];
  const float* b4 = (const float*)d_in[8];
  const float* w5 = (const float*)d_in[9];
  const float* b5 = (const float*)d_in[10];
  float* out = (float*)d_out;

  dim3 blk(16, 8);
  k1_conv1_pool<<<dim3(32, 48, B_), blk>>>(input, w1, b1);
  k2_conv2_pool<<<dim3(16, 24, 4 * B_), blk>>>(w2, b2);
  k3_conv3<<<dim3(8, 24, 2 * B_), blk>>>(w3, b3);
  k4_conv45_gray<<<dim3(8, 24, B_), blk>>>(input, w4, b4, w5, b5, out);
}